// round 8
// baseline (speedup 1.0000x reference)
#include <cuda_runtime.h>
#include <cuda_bf16.h>

#define T_      512
#define B_      512
#define EMB_    32
#define HID_    32
#define G4_     128   // 4*HID
#define FF_     16
#define NCLS_   7
#define VOCAB_  1000

typedef unsigned long long u64;

// ---------------- scratch (static device memory) ----------------------------
__device__ u64 g_tabIF[VOCAB_ * HID_];         // {xg_i, xg_f} per (v, k)
__device__ u64 g_tabGO[VOCAB_ * HID_];         // {xg_g, xg_o} per (v, k)
__device__ float g_hs[(size_t)T_ * B_ * HID_]; // 32 MB hidden states

// ---------------- fast math --------------------------------------------------
__device__ __forceinline__ float ex2f(float x) {
    float r; asm("ex2.approx.f32 %0, %1;" : "=f"(r) : "f"(x)); return r;
}
__device__ __forceinline__ float rcpf(float x) {
    float r; asm("rcp.approx.f32 %0, %1;" : "=f"(r) : "f"(x)); return r;
}
__device__ __forceinline__ float sigm_f(float x) {
    return rcpf(1.0f + ex2f(-1.4426950408889634f * x));
}
__device__ __forceinline__ float tanh_f(float x) {
    return fmaf(2.0f, rcpf(1.0f + ex2f(-2.8853900817779268f * x)), -1.0f);
}

// ---------------- packed f32x2 helpers ---------------------------------------
__device__ __forceinline__ u64 pack2(float lo, float hi) {
    u64 d; asm("mov.b64 %0, {%1, %2};" : "=l"(d) : "f"(lo), "f"(hi)); return d;
}
__device__ __forceinline__ void unpack2(u64 v, float& lo, float& hi) {
    asm("mov.b64 {%0, %1}, %2;" : "=f"(lo), "=f"(hi) : "l"(v));
}
__device__ __forceinline__ u64 ffma2(u64 a, u64 b, u64 c) {
    u64 d; asm("fma.rn.f32x2 %0, %1, %2, %3;" : "=l"(d) : "l"(a), "l"(b), "l"(c));
    return d;
}
__device__ __forceinline__ u64 fadd2(u64 a, u64 b) {
    u64 d; asm("add.rn.f32x2 %0, %1, %2;" : "=l"(d) : "l"(a), "l"(b)); return d;
}

// ---- token dtype sniff ------------------------------------------------------
__device__ __forceinline__ bool x_is_i64(const int* __restrict__ x32) {
    return (x32[1] | x32[3] | x32[5] | x32[7] | x32[9]) == 0;
}
__device__ __forceinline__ int get_tok(const int* __restrict__ x32,
                                       bool i64, int idx) {
    return x32[i64 ? (idx << 1) : idx];
}

// ---------------- K1: packed gate tables, W staged in shared ----------------
// 8 vocab entries per block; W_ih in shared (stride-33 pad: conflict-free).
__global__ __launch_bounds__(128) void k_table2(
    const float* __restrict__ emb, const float* __restrict__ W_ih,
    const float* __restrict__ b_ih, const float* __restrict__ b_hh)
{
    __shared__ float Wsh[G4_ * 33];       // [row][e] padded
    __shared__ float bsh[G4_];
    __shared__ float esh[8][EMB_];

    const int tid = threadIdx.x;
    const int v0  = blockIdx.x * 8;

#pragma unroll
    for (int i = 0; i < 32; ++i) {        // coalesced W load -> padded shared
        const int idx = tid + i * 128;
        Wsh[(idx >> 5) * 33 + (idx & 31)] = W_ih[idx];
    }
    bsh[tid] = b_ih[tid] + b_hh[tid];
#pragma unroll
    for (int i = 0; i < 2; ++i) {         // 8 emb rows = 256 floats
        const int idx = tid + i * 128;
        esh[idx >> 5][idx & 31] = emb[v0 * EMB_ + idx];
    }
    __syncthreads();

    const int gate = tid >> 5;            // 0=i 1=f 2=g 3=o
    const int k    = tid & 31;
    const int row  = gate * HID_ + k;
    const float bias = bsh[row];
    float* dstIF = reinterpret_cast<float*>(g_tabIF);
    float* dstGO = reinterpret_cast<float*>(g_tabGO);

#pragma unroll
    for (int v = 0; v < 8; ++v) {
        float acc = bias;
#pragma unroll
        for (int e = 0; e < EMB_; ++e)
            acc = fmaf(Wsh[row * 33 + e], esh[v][e], acc);
        const int vv = v0 + v;
        if (gate < 2) dstIF[vv * 64 + k * 2 + gate]       = acc;
        else          dstGO[vv * 64 + k * 2 + (gate - 2)] = acc;
    }
}

// ---------------- K2: LSTM, packed tables + 8 accumulation chains -----------
__global__ __launch_bounds__(128) void k_lstm5(
    const int* __restrict__ x, const float* __restrict__ W_hh)
{
    __shared__ int tok_s[4][T_];                       // 8 KB
    __shared__ __align__(16) u64 h_sh2[4][2][HID_];    // 2 KB, {h,h} pairs

    const int tid  = threadIdx.x;
    const int wid  = tid >> 5;
    const int lane = tid & 31;
    const int b    = blockIdx.x * 4 + wid;
    const bool i64 = x_is_i64(x);

    for (int i = lane; i < T_; i += 32)
        tok_s[wid][i] = get_tok(x, i64, i * B_ + b);

    u64 Wif[HID_], Wgo[HID_];
#pragma unroll
    for (int j = 0; j < HID_; ++j) {
        Wif[j] = pack2(W_hh[(0 * HID_ + lane) * HID_ + j],
                       W_hh[(1 * HID_ + lane) * HID_ + j]);
        Wgo[j] = pack2(W_hh[(2 * HID_ + lane) * HID_ + j],
                       W_hh[(3 * HID_ + lane) * HID_ + j]);
    }

    h_sh2[wid][0][lane] = 0ull;
    float c = 0.0f;
    int p = 0;
    __syncwarp();

    int tk = tok_s[wid][0];
    u64 xif_n = g_tabIF[tk * HID_ + lane];
    u64 xgo_n = g_tabGO[tk * HID_ + lane];

    for (int t = 0; t < T_; ++t) {
        u64 A0 = xif_n, A1 = 0ull, A2 = 0ull, A3 = 0ull;
        u64 G0 = xgo_n, G1 = 0ull, G2 = 0ull, G3 = 0ull;

        tk = tok_s[wid][(t + 1) & (T_ - 1)];
        xif_n = g_tabIF[tk * HID_ + lane];
        xgo_n = g_tabGO[tk * HID_ + lane];

        const ulonglong2* hp = reinterpret_cast<const ulonglong2*>(h_sh2[wid][p]);
#pragma unroll
        for (int q = 0; q < HID_ / 2; ++q) {
            const ulonglong2 hh = hp[q];           // {h_2q,h_2q},{h_2q+1,h_2q+1}
            if ((q & 1) == 0) {
                A0 = ffma2(Wif[2 * q + 0], hh.x, A0);
                G0 = ffma2(Wgo[2 * q + 0], hh.x, G0);
                A1 = ffma2(Wif[2 * q + 1], hh.y, A1);
                G1 = ffma2(Wgo[2 * q + 1], hh.y, G1);
            } else {
                A2 = ffma2(Wif[2 * q + 0], hh.x, A2);
                G2 = ffma2(Wgo[2 * q + 0], hh.x, G2);
                A3 = ffma2(Wif[2 * q + 1], hh.y, A3);
                G3 = ffma2(Wgo[2 * q + 1], hh.y, G3);
            }
        }
        const u64 aif = fadd2(fadd2(A0, A1), fadd2(A2, A3));
        const u64 ago = fadd2(fadd2(G0, G1), fadd2(G2, G3));

        float ai, af, ag, ao;
        unpack2(aif, ai, af);
        unpack2(ago, ag, ao);

        const float ig = sigm_f(ai);
        const float fg = sigm_f(af);
        const float gg = tanh_f(ag);
        const float og = sigm_f(ao);
        c = fmaf(fg, c, ig * gg);
        const float h = og * tanh_f(c);

        h_sh2[wid][1 - p][lane] = pack2(h, h);
        g_hs[((size_t)t * B_ + b) * HID_ + lane] = h;
        __syncwarp();
        p ^= 1;
    }
}

// ---------------- K3: FF + logits, weights in registers ----------------------
// Block = 256 rows. Stage 1: thread (f = tid&15, rg = tid>>4) computes
// z[f] for rows rg*16..+15 with W1 row f in regs; h from global (L1 broadcast).
// Stage 2: thread (c = tid>>5, l = tid&31) computes logits for rows l+32r
// with W2 row c in regs. Output staged -> coalesced float4 stores.
__global__ __launch_bounds__(256) void k_ff3(
    const float* __restrict__ W1, const float* __restrict__ b1,
    const float* __restrict__ W2, const float* __restrict__ b2,
    float* __restrict__ out)
{
    __shared__ float zsh[256 * 17];       // stride 17: conflict-free both ways
    __shared__ __align__(16) float osh[256 * NCLS_];

    const int tid = threadIdx.x;
    const size_t row0 = (size_t)blockIdx.x * 256;

    // ---- stage 1: z = relu(W1 h + b1) ----
    {
        const int f  = tid & 15;
        const int rg = tid >> 4;
        float w1r[HID_];
#pragma unroll
        for (int q = 0; q < HID_ / 4; ++q) {
            const float4 w = reinterpret_cast<const float4*>(W1)[f * 8 + q];
            w1r[q * 4 + 0] = w.x; w1r[q * 4 + 1] = w.y;
            w1r[q * 4 + 2] = w.z; w1r[q * 4 + 3] = w.w;
        }
        const float b1f = b1[f];
#pragma unroll
        for (int r = 0; r < 16; ++r) {
            const int row = rg * 16 + r;
            const float4* hp = reinterpret_cast<const float4*>(
                &g_hs[(row0 + row) * HID_]);
            float acc = b1f;
#pragma unroll
            for (int q = 0; q < HID_ / 4; ++q) {
                const float4 h4 = hp[q];
                acc = fmaf(w1r[q * 4 + 0], h4.x, acc);
                acc = fmaf(w1r[q * 4 + 1], h4.y, acc);
                acc = fmaf(w1r[q * 4 + 2], h4.z, acc);
                acc = fmaf(w1r[q * 4 + 3], h4.w, acc);
            }
            zsh[row * 17 + f] = fmaxf(acc, 0.0f);
        }
    }
    __syncthreads();

    // ---- stage 2: logits = W2 z + b2 ----
    if (tid < 224) {
        const int cl = tid >> 5;
        const int l  = tid & 31;
        float w2r[FF_];
#pragma unroll
        for (int f = 0; f < FF_; ++f) w2r[f] = W2[cl * FF_ + f];
        const float b2c = b2[cl];
#pragma unroll
        for (int r = 0; r < 8; ++r) {
            const int row = l + 32 * r;
            float acc = b2c;
#pragma unroll
            for (int f = 0; f < FF_; ++f)
                acc = fmaf(w2r[f], zsh[row * 17 + f], acc);
            osh[row * NCLS_ + cl] = acc;
        }
    }
    __syncthreads();

    // ---- coalesced store: 448 float4 per block ----
    {
        float4* out4 = reinterpret_cast<float4*>(out);
        const float4* osh4 = reinterpret_cast<const float4*>(osh);
        const size_t base4 = (size_t)blockIdx.x * 448;
#pragma unroll
        for (int i = 0; i < 2; ++i) {
            const int idx = tid + i * 256;
            if (idx < 448) out4[base4 + idx] = osh4[idx];
        }
    }
}

// ---------------- K4: softmax over T, column-parallel, in place -------------
// Flat float4 view: index t*896 + col, col in [0,896): 4 independent (b,c)
// series per column. Block = 64 threads = 16 cols x 4 t-chunks of 128.
__global__ __launch_bounds__(64) void k_softmax3(float* __restrict__ out)
{
    __shared__ float4 red[4][16];

    const int tid   = threadIdx.x;
    const int cin   = tid & 15;
    const int chunk = tid >> 4;
    const int col   = blockIdx.x * 16 + cin;
    const int t0    = chunk * 128;
    float4* o4 = reinterpret_cast<float4*>(out);

    // ---- pass 1: max over t ----
    float4 m = make_float4(-1e30f, -1e30f, -1e30f, -1e30f);
#pragma unroll 4
    for (int i = 0; i < 128; ++i) {
        const float4 v = o4[(size_t)(t0 + i) * 896 + col];
        m.x = fmaxf(m.x, v.x); m.y = fmaxf(m.y, v.y);
        m.z = fmaxf(m.z, v.z); m.w = fmaxf(m.w, v.w);
    }
    red[chunk][cin] = m;
    __syncthreads();
    {
        const float4 a = red[0][cin], b = red[1][cin];
        const float4 c = red[2][cin], d = red[3][cin];
        m.x = fmaxf(fmaxf(a.x, b.x), fmaxf(c.x, d.x));
        m.y = fmaxf(fmaxf(a.y, b.y), fmaxf(c.y, d.y));
        m.z = fmaxf(fmaxf(a.z, b.z), fmaxf(c.z, d.z));
        m.w = fmaxf(fmaxf(a.w, b.w), fmaxf(c.w, d.w));
    }
    __syncthreads();

    // ---- pass 2: sum of exp ----
    const float L2E = 1.4426950408889634f;
    float4 s = make_float4(0.f, 0.f, 0.f, 0.f);
#pragma unroll 4
    for (int i = 0; i < 128; ++i) {
        const float4 v = o4[(size_t)(t0 + i) * 896 + col];
        s.x += ex2f(L2E * (v.x - m.x));
        s.y += ex2f(L2E * (v.y - m.y));
        s.z += ex2f(L2E * (v.z - m.z));
        s.w += ex2f(L2E * (v.w - m.w));
    }
    red[chunk][cin] = s;
    __syncthreads();
    float4 R;
    {
        const float4 a = red[0][cin], b = red[1][cin];
        const float4 c = red[2][cin], d = red[3][cin];
        R.x = 1.0f / (a.x + b.x + c.x + d.x);
        R.y = 1.0f / (a.y + b.y + c.y + d.y);
        R.z = 1.0f / (a.z + b.z + c.z + d.z);
        R.w = 1.0f / (a.w + b.w + c.w + d.w);
    }

    // ---- pass 3: write normalized ----
#pragma unroll 4
    for (int i = 0; i < 128; ++i) {
        const size_t idx = (size_t)(t0 + i) * 896 + col;
        float4 v = o4[idx];
        v.x = ex2f(L2E * (v.x - m.x)) * R.x;
        v.y = ex2f(L2E * (v.y - m.y)) * R.y;
        v.z = ex2f(L2E * (v.z - m.z)) * R.z;
        v.w = ex2f(L2E * (v.w - m.w)) * R.w;
        o4[idx] = v;
    }
}

// ---------------- launch: bind by size + infer W-pair orientation -----------
extern "C" void kernel_launch(void* const* d_in, const int* in_sizes, int n_in,
                              void* d_out, int out_size)
{
    const int*   x    = nullptr;
    const float* emb  = nullptr;
    const float* Wp0  = nullptr;
    const float* Wp1  = nullptr;
    const float* b_ih = nullptr;
    const float* b_hh = nullptr;
    const float* W1   = nullptr;
    const float* b1   = nullptr;
    const float* W2   = nullptr;
    const float* b2   = nullptr;
    int idx_W1 = -1, idx_Wp0 = -1;

    for (int i = 0; i < n_in; ++i) {
        const int s = in_sizes[i];
        const void* p = d_in[i];
        switch (s) {
            case T_ * B_:
            case 2 * T_ * B_:
                if (!x) x = (const int*)p;
                break;
            case VOCAB_ * EMB_:
                emb = (const float*)p; break;
            case G4_ * EMB_:
                if (!Wp0) { Wp0 = (const float*)p; idx_Wp0 = i; }
                else      { Wp1 = (const float*)p; }
                break;
            case G4_:
                if (!b_ih) b_ih = (const float*)p; else b_hh = (const float*)p;
                break;
            case FF_ * HID_:
                W1 = (const float*)p; idx_W1 = i; break;
            case FF_:
                b1 = (const float*)p; break;
            case NCLS_ * FF_:
                W2 = (const float*)p; break;
            case NCLS_:
                b2 = (const float*)p; break;
            default: break;
        }
    }

    const bool sorted_order = (idx_W1 >= 0 && idx_Wp0 >= 0 && idx_W1 < idx_Wp0);
    const float* W_ih = sorted_order ? Wp1 : Wp0;
    const float* W_hh = sorted_order ? Wp0 : Wp1;

    float* out = (float*)d_out;

    k_table2   <<<VOCAB_ / 8, 128>>>(emb, W_ih, b_ih, b_hh);
    k_lstm5    <<<B_ / 4, 128>>>(x, W_hh);
    k_ff3      <<<(T_ * B_) / 256, 256>>>(W1, b1, W2, b2, out);
    k_softmax3 <<<896 / 16, 64>>>(out);
}

// round 9
// speedup vs baseline: 1.1369x; 1.1369x over previous
#include <cuda_runtime.h>
#include <cuda_bf16.h>

#define T_      512
#define B_      512
#define EMB_    32
#define HID_    32
#define G4_     128   // 4*HID
#define FF_     16
#define NCLS_   7
#define VOCAB_  1000

typedef unsigned long long u64;

// ---------------- scratch (static device memory) ----------------------------
__device__ u64 g_tabIF[VOCAB_ * HID_];         // {xg_i, xg_f} per (v, k)
__device__ u64 g_tabGO[VOCAB_ * HID_];         // {xg_g, xg_o} per (v, k)
__device__ float g_hs[(size_t)T_ * B_ * HID_]; // 32 MB hidden states

// ---------------- fast math --------------------------------------------------
__device__ __forceinline__ float ex2f(float x) {
    float r; asm("ex2.approx.f32 %0, %1;" : "=f"(r) : "f"(x)); return r;
}
__device__ __forceinline__ float rcpf(float x) {
    float r; asm("rcp.approx.f32 %0, %1;" : "=f"(r) : "f"(x)); return r;
}
__device__ __forceinline__ float sigm_f(float x) {
    return rcpf(1.0f + ex2f(-1.4426950408889634f * x));
}
__device__ __forceinline__ float tanh_f(float x) {
    return fmaf(2.0f, rcpf(1.0f + ex2f(-2.8853900817779268f * x)), -1.0f);
}

// ---------------- packed f32x2 helpers ---------------------------------------
__device__ __forceinline__ u64 pack2(float lo, float hi) {
    u64 d; asm("mov.b64 %0, {%1, %2};" : "=l"(d) : "f"(lo), "f"(hi)); return d;
}
__device__ __forceinline__ void unpack2(u64 v, float& lo, float& hi) {
    asm("mov.b64 {%0, %1}, %2;" : "=f"(lo), "=f"(hi) : "l"(v));
}
__device__ __forceinline__ u64 ffma2(u64 a, u64 b, u64 c) {
    u64 d; asm("fma.rn.f32x2 %0, %1, %2, %3;" : "=l"(d) : "l"(a), "l"(b), "l"(c));
    return d;
}
__device__ __forceinline__ u64 fadd2(u64 a, u64 b) {
    u64 d; asm("add.rn.f32x2 %0, %1, %2;" : "=l"(d) : "l"(a), "l"(b)); return d;
}

// ---- token dtype sniff ------------------------------------------------------
__device__ __forceinline__ bool x_is_i64(const int* __restrict__ x32) {
    return (x32[1] | x32[3] | x32[5] | x32[7] | x32[9]) == 0;
}
__device__ __forceinline__ int get_tok(const int* __restrict__ x32,
                                       bool i64, int idx) {
    return x32[i64 ? (idx << 1) : idx];
}

// ---------------- K1: packed gate tables, W staged in shared ----------------
__global__ __launch_bounds__(128) void k_table2(
    const float* __restrict__ emb, const float* __restrict__ W_ih,
    const float* __restrict__ b_ih, const float* __restrict__ b_hh)
{
    __shared__ float Wsh[G4_ * 33];       // [row][e] padded
    __shared__ float bsh[G4_];
    __shared__ float esh[8][EMB_];

    const int tid = threadIdx.x;
    const int v0  = blockIdx.x * 8;

#pragma unroll
    for (int i = 0; i < 32; ++i) {        // coalesced W load -> padded shared
        const int idx = tid + i * 128;
        Wsh[(idx >> 5) * 33 + (idx & 31)] = W_ih[idx];
    }
    bsh[tid] = b_ih[tid] + b_hh[tid];
#pragma unroll
    for (int i = 0; i < 2; ++i) {         // 8 emb rows = 256 floats
        const int idx = tid + i * 128;
        esh[idx >> 5][idx & 31] = emb[v0 * EMB_ + idx];
    }
    __syncthreads();

    const int gate = tid >> 5;            // 0=i 1=f 2=g 3=o
    const int k    = tid & 31;
    const int row  = gate * HID_ + k;
    const float bias = bsh[row];
    float* dstIF = reinterpret_cast<float*>(g_tabIF);
    float* dstGO = reinterpret_cast<float*>(g_tabGO);

#pragma unroll
    for (int v = 0; v < 8; ++v) {
        float acc = bias;
#pragma unroll
        for (int e = 0; e < EMB_; ++e)
            acc = fmaf(Wsh[row * 33 + e], esh[v][e], acc);
        const int vv = v0 + v;
        if (gate < 2) dstIF[vv * 64 + k * 2 + gate]       = acc;
        else          dstGO[vv * 64 + k * 2 + (gate - 2)] = acc;
    }
}

// ---------------- K2: LSTM, packed tables + distance-2 xg prefetch ----------
__global__ __launch_bounds__(128) void k_lstm6(
    const int* __restrict__ x, const float* __restrict__ W_hh)
{
    __shared__ int tok_s[4][T_];                       // 8 KB
    __shared__ __align__(16) u64 h_sh2[4][2][HID_];    // 2 KB, {h,h} pairs

    const int tid  = threadIdx.x;
    const int wid  = tid >> 5;
    const int lane = tid & 31;
    const int b    = blockIdx.x * 4 + wid;
    const bool i64 = x_is_i64(x);

    for (int i = lane; i < T_; i += 32)
        tok_s[wid][i] = get_tok(x, i64, i * B_ + b);

    u64 Wif[HID_], Wgo[HID_];
#pragma unroll
    for (int j = 0; j < HID_; ++j) {
        Wif[j] = pack2(W_hh[(0 * HID_ + lane) * HID_ + j],
                       W_hh[(1 * HID_ + lane) * HID_ + j]);
        Wgo[j] = pack2(W_hh[(2 * HID_ + lane) * HID_ + j],
                       W_hh[(3 * HID_ + lane) * HID_ + j]);
    }

    h_sh2[wid][0][lane] = 0ull;
    float c = 0.0f;
    int p = 0;
    __syncwarp();

    // distance-2 software pipeline on the xg gather (covers ~240cyc L2 lat)
    const int tk0 = tok_s[wid][0];
    const int tk1 = tok_s[wid][1];
    u64 cIF = g_tabIF[tk0 * HID_ + lane], cGO = g_tabGO[tk0 * HID_ + lane];
    u64 nIF = g_tabIF[tk1 * HID_ + lane], nGO = g_tabGO[tk1 * HID_ + lane];

#pragma unroll 2
    for (int t = 0; t < T_; ++t) {
        // issue loads for t+2 immediately (consumed 2 iterations later)
        const int tk2 = tok_s[wid][(t + 2) & (T_ - 1)];
        const u64 fIF = g_tabIF[tk2 * HID_ + lane];
        const u64 fGO = g_tabGO[tk2 * HID_ + lane];

        u64 A0 = cIF, A1 = 0ull, A2 = 0ull, A3 = 0ull;
        u64 G0 = cGO, G1 = 0ull, G2 = 0ull, G3 = 0ull;

        const ulonglong2* hp = reinterpret_cast<const ulonglong2*>(h_sh2[wid][p]);
#pragma unroll
        for (int q = 0; q < HID_ / 2; ++q) {
            const ulonglong2 hh = hp[q];           // {h_2q,h_2q},{h_2q+1,h_2q+1}
            if ((q & 1) == 0) {
                A0 = ffma2(Wif[2 * q + 0], hh.x, A0);
                G0 = ffma2(Wgo[2 * q + 0], hh.x, G0);
                A1 = ffma2(Wif[2 * q + 1], hh.y, A1);
                G1 = ffma2(Wgo[2 * q + 1], hh.y, G1);
            } else {
                A2 = ffma2(Wif[2 * q + 0], hh.x, A2);
                G2 = ffma2(Wgo[2 * q + 0], hh.x, G2);
                A3 = ffma2(Wif[2 * q + 1], hh.y, A3);
                G3 = ffma2(Wgo[2 * q + 1], hh.y, G3);
            }
        }
        const u64 aif = fadd2(fadd2(A0, A1), fadd2(A2, A3));
        const u64 ago = fadd2(fadd2(G0, G1), fadd2(G2, G3));

        float ai, af, ag, ao;
        unpack2(aif, ai, af);
        unpack2(ago, ag, ao);

        const float ig = sigm_f(ai);
        const float fg = sigm_f(af);
        const float gg = tanh_f(ag);
        const float og = sigm_f(ao);
        c = fmaf(fg, c, ig * gg);
        const float h = og * tanh_f(c);

        h_sh2[wid][1 - p][lane] = pack2(h, h);
        g_hs[((size_t)t * B_ + b) * HID_ + lane] = h;
        __syncwarp();
        p ^= 1;

        cIF = nIF; cGO = nGO;
        nIF = fIF; nGO = fGO;
    }
}

// ---------------- K3: FF + logits, thread-per-row, f32x2 packed weights -----
// Shared: W1 packed as w1p[j][fp] = {W1[2fp][j], W1[2fp+1][j]} (u64),
//         W2 packed as w2p[cl][fp] = {W2[cl][2fp], W2[cl][2fp+1]}.
// All shared reads are uniform-address broadcasts.
__global__ __launch_bounds__(256) void k_ff5(
    const float* __restrict__ W1, const float* __restrict__ b1,
    const float* __restrict__ W2, const float* __restrict__ b2,
    float* __restrict__ out)
{
    __shared__ u64 w1p[HID_ * 8];         // [j][fp], 2 KB
    __shared__ u64 w2p[NCLS_ * 8];        // [cl][fp]
    __shared__ u64 b1p[8];
    __shared__ float b2s[NCLS_];

    const int tid = threadIdx.x;

    if (tid < HID_ * 8) {                 // 256 threads: one pack each
        const int j  = tid >> 3;
        const int fp = tid & 7;
        w1p[j * 8 + fp] = pack2(W1[(2 * fp) * HID_ + j],
                                W1[(2 * fp + 1) * HID_ + j]);
    }
    if (tid < NCLS_ * 8) {
        const int cl = tid >> 3;
        const int fp = tid & 7;
        w2p[cl * 8 + fp] = pack2(W2[cl * FF_ + 2 * fp],
                                 W2[cl * FF_ + 2 * fp + 1]);
    }
    if (tid < 8)     b1p[tid] = pack2(b1[2 * tid], b1[2 * tid + 1]);
    if (tid < NCLS_) b2s[tid] = b2[tid];
    __syncthreads();

    const size_t r = (size_t)blockIdx.x * 256 + tid;   // flat row t*B+b

    // load h row (8 x LDG.128)
    float hv[HID_];
    const float4* hp = reinterpret_cast<const float4*>(&g_hs[r * HID_]);
#pragma unroll
    for (int q = 0; q < HID_ / 4; ++q) {
        const float4 v = hp[q];
        hv[q * 4 + 0] = v.x; hv[q * 4 + 1] = v.y;
        hv[q * 4 + 2] = v.z; hv[q * 4 + 3] = v.w;
    }

    // z = relu(W1 h + b1), 8 packed accumulators {z_2fp, z_2fp+1}
    u64 acc[8];
#pragma unroll
    for (int fp = 0; fp < 8; ++fp) acc[fp] = b1p[fp];
#pragma unroll
    for (int j = 0; j < HID_; ++j) {
        const u64 hh = pack2(hv[j], hv[j]);
#pragma unroll
        for (int fp = 0; fp < 8; ++fp)
            acc[fp] = ffma2(w1p[j * 8 + fp], hh, acc[fp]);
    }
#pragma unroll
    for (int fp = 0; fp < 8; ++fp) {      // relu on both halves
        float lo, hi;
        unpack2(acc[fp], lo, hi);
        acc[fp] = pack2(fmaxf(lo, 0.0f), fmaxf(hi, 0.0f));
    }

    // logits = W2 z + b2
    float* orow = &out[r * NCLS_];
#pragma unroll
    for (int cl = 0; cl < NCLS_; ++cl) {
        u64 a2 = 0ull;
#pragma unroll
        for (int fp = 0; fp < 8; ++fp)
            a2 = ffma2(w2p[cl * 8 + fp], acc[fp], a2);
        float lo, hi;
        unpack2(a2, lo, hi);
        orow[cl] = b2s[cl] + lo + hi;
    }
}

// ---------------- K4: softmax over T, column-parallel, single global read ---
// out viewed flat: [t][cc], cc in [0, 3584) = b*7+c. Block = 32 cols x 8
// t-chunks of 64. Warp loads 32 consecutive floats -> fully coalesced.
// Each thread buffers its 64 t-values in registers (one read pass total).
__global__ __launch_bounds__(256) void k_softmax5(float* __restrict__ out)
{
    __shared__ float red[8][32];
    const int tid   = threadIdx.x;
    const int cin   = tid & 31;
    const int chunk = tid >> 5;
    const int col   = blockIdx.x * 32 + cin;
    const int t0    = chunk * 64;
    const float L2E = 1.4426950408889634f;

    float vv[64];
    float m = -1e30f;
#pragma unroll
    for (int i = 0; i < 64; ++i) {
        vv[i] = out[(size_t)(t0 + i) * 3584 + col];
        m = fmaxf(m, vv[i]);
    }
    red[chunk][cin] = m;
    __syncthreads();
#pragma unroll
    for (int q = 0; q < 8; ++q) m = fmaxf(m, red[q][cin]);
    __syncthreads();

    float s = 0.0f;
#pragma unroll
    for (int i = 0; i < 64; ++i) {
        vv[i] = ex2f(L2E * (vv[i] - m));
        s += vv[i];
    }
    red[chunk][cin] = s;
    __syncthreads();
    s = 0.0f;
#pragma unroll
    for (int q = 0; q < 8; ++q) s += red[q][cin];
    const float R = 1.0f / s;

#pragma unroll
    for (int i = 0; i < 64; ++i)
        out[(size_t)(t0 + i) * 3584 + col] = vv[i] * R;
}

// ---------------- launch: bind by size + infer W-pair orientation -----------
extern "C" void kernel_launch(void* const* d_in, const int* in_sizes, int n_in,
                              void* d_out, int out_size)
{
    const int*   x    = nullptr;
    const float* emb  = nullptr;
    const float* Wp0  = nullptr;
    const float* Wp1  = nullptr;
    const float* b_ih = nullptr;
    const float* b_hh = nullptr;
    const float* W1   = nullptr;
    const float* b1   = nullptr;
    const float* W2   = nullptr;
    const float* b2   = nullptr;
    int idx_W1 = -1, idx_Wp0 = -1;

    for (int i = 0; i < n_in; ++i) {
        const int s = in_sizes[i];
        const void* p = d_in[i];
        switch (s) {
            case T_ * B_:
            case 2 * T_ * B_:
                if (!x) x = (const int*)p;
                break;
            case VOCAB_ * EMB_:
                emb = (const float*)p; break;
            case G4_ * EMB_:
                if (!Wp0) { Wp0 = (const float*)p; idx_Wp0 = i; }
                else      { Wp1 = (const float*)p; }
                break;
            case G4_:
                if (!b_ih) b_ih = (const float*)p; else b_hh = (const float*)p;
                break;
            case FF_ * HID_:
                W1 = (const float*)p; idx_W1 = i; break;
            case FF_:
                b1 = (const float*)p; break;
            case NCLS_ * FF_:
                W2 = (const float*)p; break;
            case NCLS_:
                b2 = (const float*)p; break;
            default: break;
        }
    }

    const bool sorted_order = (idx_W1 >= 0 && idx_Wp0 >= 0 && idx_W1 < idx_Wp0);
    const float* W_ih = sorted_order ? Wp1 : Wp0;
    const float* W_hh = sorted_order ? Wp0 : Wp1;

    float* out = (float*)d_out;

    k_table2   <<<VOCAB_ / 8, 128>>>(emb, W_ih, b_ih, b_hh);
    k_lstm6    <<<B_ / 4, 128>>>(x, W_hh);
    k_ff5      <<<(T_ * B_) / 256, 256>>>(W1, b1, W2, b2, out);
    k_softmax5 <<<3584 / 32, 256>>>(out);
}

// round 10
// speedup vs baseline: 1.3618x; 1.1978x over previous
#include <cuda_runtime.h>
#include <cuda_bf16.h>

#define T_      512
#define B_      512
#define EMB_    32
#define HID_    32
#define G4_     128   // 4*HID
#define FF_     16
#define NCLS_   7
#define VOCAB_  1000

typedef unsigned long long u64;

// Gate pre-activations are PRE-SCALED at build time:
//   i, f, o rows scaled by -log2(e); g rows scaled by -2*log2(e).
// Then sigmoid(a) = rcp(1 + 2^s_a), tanh(g) = 2*rcp(1 + 2^s_g) - 1 directly.
#define L2E_   1.4426950408889634f

// ---------------- scratch (static device memory) ----------------------------
__device__ u64 g_tabIF[VOCAB_ * HID_];         // {s_i, s_f} per (v, k), scaled
__device__ u64 g_tabGO[VOCAB_ * HID_];         // {s_g, s_o} per (v, k), scaled
__device__ float g_hs[(size_t)T_ * B_ * HID_]; // 32 MB hidden states

// ---------------- fast math --------------------------------------------------
__device__ __forceinline__ float ex2f(float x) {
    float r; asm("ex2.approx.f32 %0, %1;" : "=f"(r) : "f"(x)); return r;
}
__device__ __forceinline__ float rcpf(float x) {
    float r; asm("rcp.approx.f32 %0, %1;" : "=f"(r) : "f"(x)); return r;
}
// pre-scaled activations (argument already multiplied by -L2E / -2*L2E)
__device__ __forceinline__ float sigm_pre(float a) {   // a = -L2E*x
    return rcpf(1.0f + ex2f(a));
}
__device__ __forceinline__ float tanh_pre(float a) {   // a = -2*L2E*x
    return fmaf(2.0f, rcpf(1.0f + ex2f(a)), -1.0f);
}
__device__ __forceinline__ float tanh_f(float x) {     // unscaled arg (for c)
    return fmaf(2.0f, rcpf(1.0f + ex2f(-2.0f * L2E_ * x)), -1.0f);
}

// ---------------- packed f32x2 helpers ---------------------------------------
__device__ __forceinline__ u64 pack2(float lo, float hi) {
    u64 d; asm("mov.b64 %0, {%1, %2};" : "=l"(d) : "f"(lo), "f"(hi)); return d;
}
__device__ __forceinline__ void unpack2(u64 v, float& lo, float& hi) {
    asm("mov.b64 {%0, %1}, %2;" : "=f"(lo), "=f"(hi) : "l"(v));
}
__device__ __forceinline__ u64 ffma2(u64 a, u64 b, u64 c) {
    u64 d; asm("fma.rn.f32x2 %0, %1, %2, %3;" : "=l"(d) : "l"(a), "l"(b), "l"(c));
    return d;
}
__device__ __forceinline__ u64 fadd2(u64 a, u64 b) {
    u64 d; asm("add.rn.f32x2 %0, %1, %2;" : "=l"(d) : "l"(a), "l"(b)); return d;
}

// ---- token dtype sniff ------------------------------------------------------
__device__ __forceinline__ bool x_is_i64(const int* __restrict__ x32) {
    return (x32[1] | x32[3] | x32[5] | x32[7] | x32[9]) == 0;
}
__device__ __forceinline__ int get_tok(const int* __restrict__ x32,
                                       bool i64, int idx) {
    return x32[i64 ? (idx << 1) : idx];
}

// ---------------- K1: packed + pre-scaled gate tables -----------------------
__global__ __launch_bounds__(128) void k_table3(
    const float* __restrict__ emb, const float* __restrict__ W_ih,
    const float* __restrict__ b_ih, const float* __restrict__ b_hh)
{
    __shared__ float Wsh[G4_ * 33];       // [row][e] padded
    __shared__ float bsh[G4_];
    __shared__ float esh[8][EMB_];

    const int tid = threadIdx.x;
    const int v0  = blockIdx.x * 8;

#pragma unroll
    for (int i = 0; i < 32; ++i) {        // coalesced W load -> padded shared
        const int idx = tid + i * 128;
        Wsh[(idx >> 5) * 33 + (idx & 31)] = W_ih[idx];
    }
    bsh[tid] = b_ih[tid] + b_hh[tid];
#pragma unroll
    for (int i = 0; i < 2; ++i) {         // 8 emb rows = 256 floats
        const int idx = tid + i * 128;
        esh[idx >> 5][idx & 31] = emb[v0 * EMB_ + idx];
    }
    __syncthreads();

    const int gate = tid >> 5;            // 0=i 1=f 2=g 3=o
    const int k    = tid & 31;
    const int row  = gate * HID_ + k;
    const float bias = bsh[row];
    const float scale = (gate == 2) ? (-2.0f * L2E_) : (-L2E_);
    float* dstIF = reinterpret_cast<float*>(g_tabIF);
    float* dstGO = reinterpret_cast<float*>(g_tabGO);

#pragma unroll
    for (int v = 0; v < 8; ++v) {
        float acc = bias;
#pragma unroll
        for (int e = 0; e < EMB_; ++e)
            acc = fmaf(Wsh[row * 33 + e], esh[v][e], acc);
        acc *= scale;
        const int vv = v0 + v;
        if (gate < 2) dstIF[vv * 64 + k * 2 + gate]       = acc;
        else          dstGO[vv * 64 + k * 2 + (gate - 2)] = acc;
    }
}

// ---------------- K2: LSTM, packed scaled tables, distance-1 prefetch -------
__global__ __launch_bounds__(128) void k_lstm7(
    const int* __restrict__ x, const float* __restrict__ W_hh)
{
    __shared__ int tok_s[4][T_];                       // 8 KB
    __shared__ __align__(16) u64 h_sh2[4][2][HID_];    // 2 KB, {h,h} pairs

    const int tid  = threadIdx.x;
    const int wid  = tid >> 5;
    const int lane = tid & 31;
    const int b    = blockIdx.x * 4 + wid;
    const bool i64 = x_is_i64(x);

    for (int i = lane; i < T_; i += 32)
        tok_s[wid][i] = get_tok(x, i64, i * B_ + b);

    // packed recurrent weights with the same per-gate pre-scales
    u64 Wif[HID_], Wgo[HID_];
#pragma unroll
    for (int j = 0; j < HID_; ++j) {
        Wif[j] = pack2(-L2E_        * W_hh[(0 * HID_ + lane) * HID_ + j],
                       -L2E_        * W_hh[(1 * HID_ + lane) * HID_ + j]);
        Wgo[j] = pack2(-2.0f * L2E_ * W_hh[(2 * HID_ + lane) * HID_ + j],
                       -L2E_        * W_hh[(3 * HID_ + lane) * HID_ + j]);
    }

    h_sh2[wid][0][lane] = 0ull;
    float c = 0.0f;
    int p = 0;
    __syncwarp();

    int tk = tok_s[wid][0];
    u64 xif_n = g_tabIF[tk * HID_ + lane];
    u64 xgo_n = g_tabGO[tk * HID_ + lane];

    for (int t = 0; t < T_; ++t) {
        u64 A0 = xif_n, A1 = 0ull;
        u64 G0 = xgo_n, G1 = 0ull;

        tk = tok_s[wid][(t + 1) & (T_ - 1)];
        xif_n = g_tabIF[tk * HID_ + lane];
        xgo_n = g_tabGO[tk * HID_ + lane];

        const ulonglong2* hp = reinterpret_cast<const ulonglong2*>(h_sh2[wid][p]);
#pragma unroll
        for (int q = 0; q < HID_ / 2; ++q) {
            const ulonglong2 hh = hp[q];           // {h_2q,h_2q},{h_2q+1,h_2q+1}
            A0 = ffma2(Wif[2 * q + 0], hh.x, A0);
            G0 = ffma2(Wgo[2 * q + 0], hh.x, G0);
            A1 = ffma2(Wif[2 * q + 1], hh.y, A1);
            G1 = ffma2(Wgo[2 * q + 1], hh.y, G1);
        }
        const u64 aif = fadd2(A0, A1);
        const u64 ago = fadd2(G0, G1);

        float ai, af, ag, ao;
        unpack2(aif, ai, af);
        unpack2(ago, ag, ao);

        // pre-scaled: no leading multiply in the activation chain
        const float ig = sigm_pre(ai);
        const float fg = sigm_pre(af);
        const float gg = tanh_pre(ag);
        const float og = sigm_pre(ao);
        c = fmaf(fg, c, ig * gg);
        const float h = og * tanh_f(c);

        h_sh2[wid][1 - p][lane] = pack2(h, h);
        g_hs[((size_t)t * B_ + b) * HID_ + lane] = h;
        __syncwarp();
        p ^= 1;
    }
}

// ---------------- K3: FF + logits, thread-per-row, f32x2 packed weights -----
__global__ __launch_bounds__(256) void k_ff5(
    const float* __restrict__ W1, const float* __restrict__ b1,
    const float* __restrict__ W2, const float* __restrict__ b2,
    float* __restrict__ out)
{
    __shared__ u64 w1p[HID_ * 8];         // [j][fp], 2 KB
    __shared__ u64 w2p[NCLS_ * 8];        // [cl][fp]
    __shared__ u64 b1p[8];
    __shared__ float b2s[NCLS_];

    const int tid = threadIdx.x;

    if (tid < HID_ * 8) {
        const int j  = tid >> 3;
        const int fp = tid & 7;
        w1p[j * 8 + fp] = pack2(W1[(2 * fp) * HID_ + j],
                                W1[(2 * fp + 1) * HID_ + j]);
    }
    if (tid < NCLS_ * 8) {
        const int cl = tid >> 3;
        const int fp = tid & 7;
        w2p[cl * 8 + fp] = pack2(W2[cl * FF_ + 2 * fp],
                                 W2[cl * FF_ + 2 * fp + 1]);
    }
    if (tid < 8)     b1p[tid] = pack2(b1[2 * tid], b1[2 * tid + 1]);
    if (tid < NCLS_) b2s[tid] = b2[tid];
    __syncthreads();

    const size_t r = (size_t)blockIdx.x * 256 + tid;   // flat row t*B+b

    float hv[HID_];
    const float4* hp = reinterpret_cast<const float4*>(&g_hs[r * HID_]);
#pragma unroll
    for (int q = 0; q < HID_ / 4; ++q) {
        const float4 v = hp[q];
        hv[q * 4 + 0] = v.x; hv[q * 4 + 1] = v.y;
        hv[q * 4 + 2] = v.z; hv[q * 4 + 3] = v.w;
    }

    u64 acc[8];
#pragma unroll
    for (int fp = 0; fp < 8; ++fp) acc[fp] = b1p[fp];
#pragma unroll
    for (int j = 0; j < HID_; ++j) {
        const u64 hh = pack2(hv[j], hv[j]);
#pragma unroll
        for (int fp = 0; fp < 8; ++fp)
            acc[fp] = ffma2(w1p[j * 8 + fp], hh, acc[fp]);
    }
#pragma unroll
    for (int fp = 0; fp < 8; ++fp) {
        float lo, hi;
        unpack2(acc[fp], lo, hi);
        acc[fp] = pack2(fmaxf(lo, 0.0f), fmaxf(hi, 0.0f));
    }

    float* orow = &out[r * NCLS_];
#pragma unroll
    for (int cl = 0; cl < NCLS_; ++cl) {
        u64 a2 = 0ull;
#pragma unroll
        for (int fp = 0; fp < 8; ++fp)
            a2 = ffma2(w2p[cl * 8 + fp], acc[fp], a2);
        float lo, hi;
        unpack2(a2, lo, hi);
        orow[cl] = b2s[cl] + lo + hi;
    }
}

// ---------------- K4: softmax over T, column-parallel, single global read ---
__global__ __launch_bounds__(256) void k_softmax5(float* __restrict__ out)
{
    __shared__ float red[8][32];
    const int tid   = threadIdx.x;
    const int cin   = tid & 31;
    const int chunk = tid >> 5;
    const int col   = blockIdx.x * 32 + cin;
    const int t0    = chunk * 64;

    float vv[64];
    float m = -1e30f;
#pragma unroll
    for (int i = 0; i < 64; ++i) {
        vv[i] = out[(size_t)(t0 + i) * 3584 + col];
        m = fmaxf(m, vv[i]);
    }
    red[chunk][cin] = m;
    __syncthreads();
#pragma unroll
    for (int q = 0; q < 8; ++q) m = fmaxf(m, red[q][cin]);
    __syncthreads();

    float s = 0.0f;
#pragma unroll
    for (int i = 0; i < 64; ++i) {
        vv[i] = ex2f(L2E_ * (vv[i] - m));
        s += vv[i];
    }
    red[chunk][cin] = s;
    __syncthreads();
    s = 0.0f;
#pragma unroll
    for (int q = 0; q < 8; ++q) s += red[q][cin];
    const float R = 1.0f / s;

#pragma unroll
    for (int i = 0; i < 64; ++i)
        out[(size_t)(t0 + i) * 3584 + col] = vv[i] * R;
}

// ---------------- launch: bind by size + infer W-pair orientation -----------
extern "C" void kernel_launch(void* const* d_in, const int* in_sizes, int n_in,
                              void* d_out, int out_size)
{
    const int*   x    = nullptr;
    const float* emb  = nullptr;
    const float* Wp0  = nullptr;
    const float* Wp1  = nullptr;
    const float* b_ih = nullptr;
    const float* b_hh = nullptr;
    const float* W1   = nullptr;
    const float* b1   = nullptr;
    const float* W2   = nullptr;
    const float* b2   = nullptr;
    int idx_W1 = -1, idx_Wp0 = -1;

    for (int i = 0; i < n_in; ++i) {
        const int s = in_sizes[i];
        const void* p = d_in[i];
        switch (s) {
            case T_ * B_:
            case 2 * T_ * B_:
                if (!x) x = (const int*)p;
                break;
            case VOCAB_ * EMB_:
                emb = (const float*)p; break;
            case G4_ * EMB_:
                if (!Wp0) { Wp0 = (const float*)p; idx_Wp0 = i; }
                else      { Wp1 = (const float*)p; }
                break;
            case G4_:
                if (!b_ih) b_ih = (const float*)p; else b_hh = (const float*)p;
                break;
            case FF_ * HID_:
                W1 = (const float*)p; idx_W1 = i; break;
            case FF_:
                b1 = (const float*)p; break;
            case NCLS_ * FF_:
                W2 = (const float*)p; break;
            case NCLS_:
                b2 = (const float*)p; break;
            default: break;
        }
    }

    const bool sorted_order = (idx_W1 >= 0 && idx_Wp0 >= 0 && idx_W1 < idx_Wp0);
    const float* W_ih = sorted_order ? Wp1 : Wp0;
    const float* W_hh = sorted_order ? Wp0 : Wp1;

    float* out = (float*)d_out;

    k_table3   <<<VOCAB_ / 8, 128>>>(emb, W_ih, b_ih, b_hh);
    k_lstm7    <<<B_ / 4, 128>>>(x, W_hh);
    k_ff5      <<<(T_ * B_) / 256, 256>>>(W1, b1, W2, b2, out);
    k_softmax5 <<<3584 / 32, 256>>>(out);
}

// round 11
// speedup vs baseline: 1.6081x; 1.1808x over previous
#include <cuda_runtime.h>
#include <cuda_bf16.h>

#define T_      512
#define B_      512
#define EMB_    32
#define HID_    32
#define G4_     128   // 4*HID
#define FF_     16
#define NCLS_   7
#define VOCAB_  1000

typedef unsigned long long u64;

#define L2E_   1.4426950408889634f

// Gate pre-activations are PRE-SCALED at build time for the tanh identity:
//   sigmoid(x) = 0.5*tanh(0.5x) + 0.5  -> i, f, o rows scaled by 0.5
//   tanh(x)    = tanh.approx directly  -> g row unscaled

// ---------------- scratch (static device memory) ----------------------------
__device__ u64 g_tabIF[VOCAB_ * HID_];         // {0.5*a_i, 0.5*a_f} per (v,k)
__device__ u64 g_tabGO[VOCAB_ * HID_];         // {a_g, 0.5*a_o} per (v,k)
__device__ float g_hs[(size_t)T_ * B_ * HID_]; // 32 MB hidden states

// ---------------- fast math --------------------------------------------------
__device__ __forceinline__ float ex2f(float x) {
    float r; asm("ex2.approx.f32 %0, %1;" : "=f"(r) : "f"(x)); return r;
}
__device__ __forceinline__ float tanhap(float x) {
    float r; asm("tanh.approx.f32 %0, %1;" : "=f"(r) : "f"(x)); return r;
}
// sigmoid with pre-halved argument: sg(a) = 0.5*tanh(a) + 0.5,  a = 0.5*x
__device__ __forceinline__ float sigm_h(float a) {
    return fmaf(0.5f, tanhap(a), 0.5f);
}

// ---------------- packed f32x2 helpers ---------------------------------------
__device__ __forceinline__ u64 pack2(float lo, float hi) {
    u64 d; asm("mov.b64 %0, {%1, %2};" : "=l"(d) : "f"(lo), "f"(hi)); return d;
}
__device__ __forceinline__ void unpack2(u64 v, float& lo, float& hi) {
    asm("mov.b64 {%0, %1}, %2;" : "=f"(lo), "=f"(hi) : "l"(v));
}
__device__ __forceinline__ u64 ffma2(u64 a, u64 b, u64 c) {
    u64 d; asm("fma.rn.f32x2 %0, %1, %2, %3;" : "=l"(d) : "l"(a), "l"(b), "l"(c));
    return d;
}
__device__ __forceinline__ u64 fadd2(u64 a, u64 b) {
    u64 d; asm("add.rn.f32x2 %0, %1, %2;" : "=l"(d) : "l"(a), "l"(b)); return d;
}

// ---- token dtype sniff ------------------------------------------------------
__device__ __forceinline__ bool x_is_i64(const int* __restrict__ x32) {
    return (x32[1] | x32[3] | x32[5] | x32[7] | x32[9]) == 0;
}
__device__ __forceinline__ int get_tok(const int* __restrict__ x32,
                                       bool i64, int idx) {
    return x32[i64 ? (idx << 1) : idx];
}

// ---------------- K1: packed + half-scaled gate tables ----------------------
__global__ __launch_bounds__(128) void k_table4(
    const float* __restrict__ emb, const float* __restrict__ W_ih,
    const float* __restrict__ b_ih, const float* __restrict__ b_hh)
{
    __shared__ float Wsh[G4_ * 33];       // [row][e] padded
    __shared__ float bsh[G4_];
    __shared__ float esh[8][EMB_];

    const int tid = threadIdx.x;
    const int v0  = blockIdx.x * 8;

#pragma unroll
    for (int i = 0; i < 32; ++i) {
        const int idx = tid + i * 128;
        Wsh[(idx >> 5) * 33 + (idx & 31)] = W_ih[idx];
    }
    bsh[tid] = b_ih[tid] + b_hh[tid];
#pragma unroll
    for (int i = 0; i < 2; ++i) {
        const int idx = tid + i * 128;
        esh[idx >> 5][idx & 31] = emb[v0 * EMB_ + idx];
    }
    __syncthreads();

    const int gate = tid >> 5;            // 0=i 1=f 2=g 3=o
    const int k    = tid & 31;
    const int row  = gate * HID_ + k;
    const float bias = bsh[row];
    const float scale = (gate == 2) ? 1.0f : 0.5f;
    float* dstIF = reinterpret_cast<float*>(g_tabIF);
    float* dstGO = reinterpret_cast<float*>(g_tabGO);

#pragma unroll
    for (int v = 0; v < 8; ++v) {
        float acc = bias;
#pragma unroll
        for (int e = 0; e < EMB_; ++e)
            acc = fmaf(Wsh[row * 33 + e], esh[v][e], acc);
        acc *= scale;
        const int vv = v0 + v;
        if (gate < 2) dstIF[vv * 64 + k * 2 + gate]       = acc;
        else          dstGO[vv * 64 + k * 2 + (gate - 2)] = acc;
    }
}

// ---------------- K2: LSTM, shfl h-exchange + MUFU tanh activations ---------
__global__ __launch_bounds__(128) void k_lstm8(
    const int* __restrict__ x, const float* __restrict__ W_hh)
{
    __shared__ int tok_s[4][T_];                       // 8 KB

    const int tid  = threadIdx.x;
    const int wid  = tid >> 5;
    const int lane = tid & 31;
    const int b    = blockIdx.x * 4 + wid;
    const bool i64 = x_is_i64(x);

    for (int i = lane; i < T_; i += 32)
        tok_s[wid][i] = get_tok(x, i64, i * B_ + b);
    __syncwarp();

    // packed recurrent weights, pre-scaled: i,f,o x0.5; g x1
    u64 Wif[HID_], Wgo[HID_];
#pragma unroll
    for (int j = 0; j < HID_; ++j) {
        Wif[j] = pack2(0.5f * W_hh[(0 * HID_ + lane) * HID_ + j],
                       0.5f * W_hh[(1 * HID_ + lane) * HID_ + j]);
        Wgo[j] = pack2(       W_hh[(2 * HID_ + lane) * HID_ + j],
                       0.5f * W_hh[(3 * HID_ + lane) * HID_ + j]);
    }

    float h = 0.0f, c = 0.0f;

    int tk = tok_s[wid][0];
    u64 xif_n = g_tabIF[tk * HID_ + lane];
    u64 xgo_n = g_tabGO[tk * HID_ + lane];

    for (int t = 0; t < T_; ++t) {
        u64 A0 = xif_n, A1 = 0ull;
        u64 G0 = xgo_n, G1 = 0ull;

        tk = tok_s[wid][(t + 1) & (T_ - 1)];
        xif_n = g_tabIF[tk * HID_ + lane];
        xgo_n = g_tabGO[tk * HID_ + lane];

        // recurrence: h_j broadcast via shfl (no shared, no explicit sync)
#pragma unroll
        for (int j = 0; j < HID_; j += 2) {
            const float hj0 = __shfl_sync(0xffffffffu, h, j);
            const float hj1 = __shfl_sync(0xffffffffu, h, j + 1);
            const u64 hh0 = pack2(hj0, hj0);
            const u64 hh1 = pack2(hj1, hj1);
            A0 = ffma2(Wif[j],     hh0, A0);
            G0 = ffma2(Wgo[j],     hh0, G0);
            A1 = ffma2(Wif[j + 1], hh1, A1);
            G1 = ffma2(Wgo[j + 1], hh1, G1);
        }
        const u64 aif = fadd2(A0, A1);
        const u64 ago = fadd2(G0, G1);

        float ai, af, ag, ao;
        unpack2(aif, ai, af);
        unpack2(ago, ag, ao);

        const float ig = sigm_h(ai);       // tanh + fma
        const float fg = sigm_h(af);
        const float gg = tanhap(ag);       // single MUFU
        const float og = sigm_h(ao);
        c = fmaf(fg, c, ig * gg);
        h = og * tanhap(c);                // single MUFU on the chain

        g_hs[((size_t)t * B_ + b) * HID_ + lane] = h;  // coalesced 128B/warp
    }
}

// ---------------- K3: FF + logits, thread-per-row, f32x2 packed weights -----
__global__ __launch_bounds__(256) void k_ff5(
    const float* __restrict__ W1, const float* __restrict__ b1,
    const float* __restrict__ W2, const float* __restrict__ b2,
    float* __restrict__ out)
{
    __shared__ u64 w1p[HID_ * 8];         // [j][fp], 2 KB
    __shared__ u64 w2p[NCLS_ * 8];        // [cl][fp]
    __shared__ u64 b1p[8];
    __shared__ float b2s[NCLS_];

    const int tid = threadIdx.x;

    if (tid < HID_ * 8) {
        const int j  = tid >> 3;
        const int fp = tid & 7;
        w1p[j * 8 + fp] = pack2(W1[(2 * fp) * HID_ + j],
                                W1[(2 * fp + 1) * HID_ + j]);
    }
    if (tid < NCLS_ * 8) {
        const int cl = tid >> 3;
        const int fp = tid & 7;
        w2p[cl * 8 + fp] = pack2(W2[cl * FF_ + 2 * fp],
                                 W2[cl * FF_ + 2 * fp + 1]);
    }
    if (tid < 8)     b1p[tid] = pack2(b1[2 * tid], b1[2 * tid + 1]);
    if (tid < NCLS_) b2s[tid] = b2[tid];
    __syncthreads();

    const size_t r = (size_t)blockIdx.x * 256 + tid;   // flat row t*B+b

    float hv[HID_];
    const float4* hp = reinterpret_cast<const float4*>(&g_hs[r * HID_]);
#pragma unroll
    for (int q = 0; q < HID_ / 4; ++q) {
        const float4 v = hp[q];
        hv[q * 4 + 0] = v.x; hv[q * 4 + 1] = v.y;
        hv[q * 4 + 2] = v.z; hv[q * 4 + 3] = v.w;
    }

    u64 acc[8];
#pragma unroll
    for (int fp = 0; fp < 8; ++fp) acc[fp] = b1p[fp];
#pragma unroll
    for (int j = 0; j < HID_; ++j) {
        const u64 hh = pack2(hv[j], hv[j]);
#pragma unroll
        for (int fp = 0; fp < 8; ++fp)
            acc[fp] = ffma2(w1p[j * 8 + fp], hh, acc[fp]);
    }
#pragma unroll
    for (int fp = 0; fp < 8; ++fp) {
        float lo, hi;
        unpack2(acc[fp], lo, hi);
        acc[fp] = pack2(fmaxf(lo, 0.0f), fmaxf(hi, 0.0f));
    }

    float* orow = &out[r * NCLS_];
#pragma unroll
    for (int cl = 0; cl < NCLS_; ++cl) {
        u64 a2 = 0ull;
#pragma unroll
        for (int fp = 0; fp < 8; ++fp)
            a2 = ffma2(w2p[cl * 8 + fp], acc[fp], a2);
        float lo, hi;
        unpack2(a2, lo, hi);
        orow[cl] = b2s[cl] + lo + hi;
    }
}

// ---------------- K4: softmax over T, column-parallel, single global read ---
__global__ __launch_bounds__(256) void k_softmax5(float* __restrict__ out)
{
    __shared__ float red[8][32];
    const int tid   = threadIdx.x;
    const int cin   = tid & 31;
    const int chunk = tid >> 5;
    const int col   = blockIdx.x * 32 + cin;
    const int t0    = chunk * 64;

    float vv[64];
    float m = -1e30f;
#pragma unroll
    for (int i = 0; i < 64; ++i) {
        vv[i] = out[(size_t)(t0 + i) * 3584 + col];
        m = fmaxf(m, vv[i]);
    }
    red[chunk][cin] = m;
    __syncthreads();
#pragma unroll
    for (int q = 0; q < 8; ++q) m = fmaxf(m, red[q][cin]);
    __syncthreads();

    float s = 0.0f;
#pragma unroll
    for (int i = 0; i < 64; ++i) {
        vv[i] = ex2f(L2E_ * (vv[i] - m));
        s += vv[i];
    }
    red[chunk][cin] = s;
    __syncthreads();
    s = 0.0f;
#pragma unroll
    for (int q = 0; q < 8; ++q) s += red[q][cin];
    const float R = 1.0f / s;

#pragma unroll
    for (int i = 0; i < 64; ++i)
        out[(size_t)(t0 + i) * 3584 + col] = vv[i] * R;
}

// ---------------- launch: bind by size + infer W-pair orientation -----------
extern "C" void kernel_launch(void* const* d_in, const int* in_sizes, int n_in,
                              void* d_out, int out_size)
{
    const int*   x    = nullptr;
    const float* emb  = nullptr;
    const float* Wp0  = nullptr;
    const float* Wp1  = nullptr;
    const float* b_ih = nullptr;
    const float* b_hh = nullptr;
    const float* W1   = nullptr;
    const float* b1   = nullptr;
    const float* W2   = nullptr;
    const float* b2   = nullptr;
    int idx_W1 = -1, idx_Wp0 = -1;

    for (int i = 0; i < n_in; ++i) {
        const int s = in_sizes[i];
        const void* p = d_in[i];
        switch (s) {
            case T_ * B_:
            case 2 * T_ * B_:
                if (!x) x = (const int*)p;
                break;
            case VOCAB_ * EMB_:
                emb = (const float*)p; break;
            case G4_ * EMB_:
                if (!Wp0) { Wp0 = (const float*)p; idx_Wp0 = i; }
                else      { Wp1 = (const float*)p; }
                break;
            case G4_:
                if (!b_ih) b_ih = (const float*)p; else b_hh = (const float*)p;
                break;
            case FF_ * HID_:
                W1 = (const float*)p; idx_W1 = i; break;
            case FF_:
                b1 = (const float*)p; break;
            case NCLS_ * FF_:
                W2 = (const float*)p; break;
            case NCLS_:
                b2 = (const float*)p; break;
            default: break;
        }
    }

    const bool sorted_order = (idx_W1 >= 0 && idx_Wp0 >= 0 && idx_W1 < idx_Wp0);
    const float* W_ih = sorted_order ? Wp1 : Wp0;
    const float* W_hh = sorted_order ? Wp0 : Wp1;

    float* out = (float*)d_out;

    k_table4   <<<VOCAB_ / 8, 128>>>(emb, W_ih, b_ih, b_hh);
    k_lstm8    <<<B_ / 4, 128>>>(x, W_hh);
    k_ff5      <<<(T_ * B_) / 256, 256>>>(W1, b1, W2, b2, out);
    k_softmax5 <<<3584 / 32, 256>>>(out);
}